// round 13
// baseline (speedup 1.0000x reference)
#include <cuda_runtime.h>
#include <cuda_bf16.h>
#include <math.h>
#include <stdint.h>

#define LNUM 4
#define D 1024
#define H 16
#define KVH 4
#define HD 64
#define NE 8
#define TOPK 2
#define FF 512
#define NV 32000
#define NB 2
#define NT 1024
#define NTOK (NB*NT)        // 2048
#define NSLOT (NTOK*TOPK)   // 4096
#define EPSV 1e-6f

// ---------------- scratch (static device globals; no allocs) ----------------
__device__ float g_x[NTOK*D];
__device__ float g_xn[NTOK*D];
__device__ float g_q[NTOK*H*HD];
__device__ float g_k[NTOK*KVH*HD];
__device__ float g_v[NTOK*KVH*HD];
__device__ float g_att[NTOK*H*HD];
__device__ float g_gbuf[NSLOT*FF];
__device__ float g_ubuf[NSLOT*FF];
__device__ float g_ybuf[NSLOT*D];
__device__ float g_xmean[NB*D];
__device__ int   g_topk_idx[NTOK*TOPK];
__device__ float g_topk_gate[NTOK*TOPK];
__device__ int   g_count[NE];
__device__ int   g_offset[NE];
__device__ int   g_fill[NE];
__device__ float g_mesum[NE];
__device__ int   g_slot_token[NSLOT];
__device__ int   g_slot_of[NTOK*TOPK];
__device__ float g_aux[1];
// split-bf16 copies for the tensor-core lm_head
// weights stored TRANSPOSED: [NV][D] (n-major) for mma.sync col-B operand
__device__ __nv_bfloat16 g_lmw_h[(size_t)NV*D];
__device__ __nv_bfloat16 g_lmw_l[(size_t)NV*D];
__device__ __nv_bfloat16 g_xh[NTOK*D];
__device__ __nv_bfloat16 g_xl[NTOK*D];

// ==================== smem address helper ============================
__device__ __forceinline__ uint32_t smem_u32(const void* p) {
    uint32_t a;
    asm("{ .reg .u64 t; cvta.to.shared.u64 t, %1; cvt.u32.u64 %0, t; }" : "=r"(a) : "l"(p));
    return a;
}

#define LDSM4(r, addr) \
    asm volatile("ldmatrix.sync.aligned.m8n8.x4.shared.b16 {%0,%1,%2,%3}, [%4];" \
        : "=r"((r)[0]), "=r"((r)[1]), "=r"((r)[2]), "=r"((r)[3]) : "r"(addr))

#define MMA_BF16(c, a, b0, b1) \
    asm volatile("mma.sync.aligned.m16n8k16.row.col.f32.bf16.bf16.f32 " \
        "{%0,%1,%2,%3}, {%4,%5,%6,%7}, {%8,%9}, {%0,%1,%2,%3};" \
        : "+f"((c)[0]), "+f"((c)[1]), "+f"((c)[2]), "+f"((c)[3]) \
        : "r"((a)[0]), "r"((a)[1]), "r"((a)[2]), "r"((a)[3]), "r"(b0), "r"(b1))

// ==================== split fp32 -> bf16 hi/lo (same layout) ===============
__global__ void split_bf16_kernel(const float* __restrict__ src,
                                  __nv_bfloat16* __restrict__ hi,
                                  __nv_bfloat16* __restrict__ lo) {
    size_t i = (size_t)blockIdx.x * 256 + threadIdx.x;
    float4 v = *(const float4*)(src + i * 4);
    float vv[4] = {v.x, v.y, v.z, v.w};
    ushort4 hb, lb;
    unsigned short* hp = &hb.x;
    unsigned short* lp = &lb.x;
    #pragma unroll
    for (int j = 0; j < 4; j++) {
        __nv_bfloat16 h = __float2bfloat16(vv[j]);
        __nv_bfloat16 l = __float2bfloat16(vv[j] - __bfloat162float(h));
        hp[j] = __bfloat16_as_ushort(h);
        lp[j] = __bfloat16_as_ushort(l);
    }
    *(ushort4*)((unsigned short*)hi + i * 4) = hb;
    *(ushort4*)((unsigned short*)lo + i * 4) = lb;
}

// ==================== transposed split: src [D][NV] -> hi/lo [NV][D] ========
__global__ void split_bf16_T_kernel(const float* __restrict__ src,
                                    __nv_bfloat16* __restrict__ hi,
                                    __nv_bfloat16* __restrict__ lo) {
    __shared__ float t[32][33];
    int n0 = blockIdx.x * 32, k0 = blockIdx.y * 32;
    int tx = threadIdx.x & 31, ty = threadIdx.x >> 5;   // 32 x 8
    #pragma unroll
    for (int i = 0; i < 4; i++)
        t[ty + i * 8][tx] = src[(size_t)(k0 + ty + i * 8) * NV + n0 + tx];
    __syncthreads();
    #pragma unroll
    for (int i = 0; i < 4; i++) {
        int n = ty + i * 8;
        float v = t[tx][n];       // = src[k0+tx][n0+n]
        __nv_bfloat16 h = __float2bfloat16(v);
        __nv_bfloat16 l = __float2bfloat16(v - __bfloat162float(h));
        hi[(size_t)(n0 + n) * D + k0 + tx] = h;
        lo[(size_t)(n0 + n) * D + k0 + tx] = l;
    }
}

// ==================== lm_head via mma.sync (HMMA, portable) =================
// C[2048,32000] = A[2048,1024] @ B^T, A row-major [M][K], B n-major [N][K].
// Split-bf16: C = Ah*Bh + Ah*Bl + Al*Bh (fp32 accum). Tile 128x128x32.
#define LPAD 40                              // smem row stride (bf16 elems)
#define LTILE (128*LPAD*2)                   // 10240 B per tile
#define LBUF  (4*LTILE)                      // Ah|Al|Bh|Bl = 40960 B
#define LSM_TOTAL (2*LBUF)                   // 81920 B
__global__ void __launch_bounds__(256) lmhead_mma_kernel(
    const __nv_bfloat16* __restrict__ Ah, const __nv_bfloat16* __restrict__ Al,
    const __nv_bfloat16* __restrict__ BhT, const __nv_bfloat16* __restrict__ BlT,
    float* __restrict__ out)
{
    extern __shared__ char smem[];
    const int tid = threadIdx.x, wid = tid >> 5, lane = tid & 31;
    const int m0 = blockIdx.x * 128, n0 = blockIdx.y * 128;
    const int wm = (wid & 1) * 64, wn = (wid >> 1) * 32;
    uint32_t sb = smem_u32(smem);

    float acc[4][4][4];
    #pragma unroll
    for (int mi = 0; mi < 4; mi++)
        #pragma unroll
        for (int ni = 0; ni < 4; ni++)
            #pragma unroll
            for (int e = 0; e < 4; e++) acc[mi][ni][e] = 0.f;

    const int lrow = tid >> 3;          // 0..31
    const int lcol = (tid & 7) * 4;     // 0,4,...,28
    ushort4 ra[2][4], rb[2][4];

    auto ldg_tiles = [&](int ks) {
        int k0 = ks * 32;
        #pragma unroll
        for (int p = 0; p < 4; p++) {
            int arow = m0 + lrow + p * 32;
            int brow = n0 + lrow + p * 32;
            ra[0][p] = *(const ushort4*)(Ah  + (size_t)arow * D + k0 + lcol);
            ra[1][p] = *(const ushort4*)(Al  + (size_t)arow * D + k0 + lcol);
            rb[0][p] = *(const ushort4*)(BhT + (size_t)brow * D + k0 + lcol);
            rb[1][p] = *(const ushort4*)(BlT + (size_t)brow * D + k0 + lcol);
        }
    };
    auto sts_tiles = [&](int buf) {
        char* base = smem + buf * LBUF;
        #pragma unroll
        for (int p = 0; p < 4; p++) {
            uint32_t off = ((lrow + p * 32) * LPAD + lcol) * 2;
            *(ushort4*)(base + off)             = ra[0][p];
            *(ushort4*)(base + LTILE + off)     = ra[1][p];
            *(ushort4*)(base + 2 * LTILE + off) = rb[0][p];
            *(ushort4*)(base + 3 * LTILE + off) = rb[1][p];
        }
    };

    ldg_tiles(0);
    sts_tiles(0);
    __syncthreads();

    for (int ks = 0; ks < 32; ks++) {
        int cur = ks & 1;
        if (ks + 1 < 32) ldg_tiles(ks + 1);
        uint32_t ab  = sb + cur * LBUF;
        uint32_t alb = ab + LTILE;
        uint32_t bb  = ab + 2 * LTILE;
        uint32_t blb = ab + 3 * LTILE;
        #pragma unroll
        for (int kk = 0; kk < 2; kk++) {
            uint32_t ah[4][4], al[4][4], bh[2][4], bl[2][4];
            int acol = kk * 16 + (lane >> 4) * 8;
            #pragma unroll
            for (int mi = 0; mi < 4; mi++) {
                uint32_t off = ((wm + mi * 16 + (lane & 15)) * LPAD + acol) * 2;
                LDSM4(ah[mi], ab + off);
                LDSM4(al[mi], alb + off);
            }
            int bcol = kk * 16 + ((lane >> 3) & 1) * 8;
            #pragma unroll
            for (int g = 0; g < 2; g++) {
                int nrow = wn + g * 16 + ((lane >> 4) << 3) + (lane & 7);
                uint32_t off = (nrow * LPAD + bcol) * 2;
                LDSM4(bh[g], bb + off);
                LDSM4(bl[g], blb + off);
            }
            #pragma unroll
            for (int mi = 0; mi < 4; mi++)
                #pragma unroll
                for (int ni = 0; ni < 4; ni++) {
                    int g = ni >> 1, s = (ni & 1) * 2;
                    MMA_BF16(acc[mi][ni], ah[mi], bh[g][s], bh[g][s + 1]);
                    MMA_BF16(acc[mi][ni], ah[mi], bl[g][s], bl[g][s + 1]);
                    MMA_BF16(acc[mi][ni], al[mi], bh[g][s], bh[g][s + 1]);
                }
        }
        __syncthreads();
        if (ks + 1 < 32) {
            sts_tiles((ks + 1) & 1);
            __syncthreads();
        }
    }

    // epilogue: c0,c1 -> (row, col..col+1); c2,c3 -> (row+8, col..col+1)
    #pragma unroll
    for (int mi = 0; mi < 4; mi++) {
        int row = m0 + wm + mi * 16 + (lane >> 2);
        #pragma unroll
        for (int ni = 0; ni < 4; ni++) {
            int col = n0 + wn + ni * 8 + (lane & 3) * 2;
            float* p = out + (size_t)row * NV + col;
            float2 v0 = make_float2(acc[mi][ni][0], acc[mi][ni][1]);
            float2 v1 = make_float2(acc[mi][ni][2], acc[mi][ni][3]);
            *(float2*)p = v0;
            *(float2*)(p + (size_t)8 * NV) = v1;
        }
    }
}

// ---------------- embedding ----------------
__global__ void embed_kernel(const int* __restrict__ ids, const float* __restrict__ emb) {
    int n = blockIdx.x;
    int id = ids[n];
    int d = threadIdx.x * 4;
    float4 v = *(const float4*)(emb + (size_t)id * D + d);
    *(float4*)(g_x + (size_t)n * D + d) = v;
}

// ---------------- rmsnorm ----------------
__global__ void rmsnorm_kernel(const float* __restrict__ w,
                               const float* __restrict__ src,
                               float* __restrict__ dst) {
    int n = blockIdx.x, tid = threadIdx.x;
    const float* x = src + (size_t)n * D;
    float ss = 0.f;
    for (int d = tid; d < D; d += 256) { float v = x[d]; ss += v * v; }
    __shared__ float red[256];
    red[tid] = ss; __syncthreads();
    for (int off = 128; off > 0; off >>= 1) {
        if (tid < off) red[tid] += red[tid + off];
        __syncthreads();
    }
    __shared__ float s_scale;
    if (tid == 0) s_scale = rsqrtf(red[0] / (float)D + EPSV);
    __syncthreads();
    float sc = s_scale;
    float* o = dst + (size_t)n * D;
    for (int d = tid; d < D; d += 256) o[d] = w[d] * x[d] * sc;
}

// ---------------- generic SGEMM: C[M,N] = A[M,K] @ B[K,N] (+C if acc) ------
#define BM 128
#define BN 128
#define BKT 8
__global__ void __launch_bounds__(256) gemm_kernel(
    int M, int N, int K,
    const float* __restrict__ A, int lda,
    const float* __restrict__ B, int ldb,
    float* __restrict__ C, int ldc, int accflag)
{
    __shared__ float As[BKT][BM];
    __shared__ float Bs[BKT][BN];
    int bm = blockIdx.y * BM, bn = blockIdx.x * BN;
    int tid = threadIdx.x;
    int tx = tid & 15, ty = tid >> 4;
    int ar = tid >> 1, ac = (tid & 1) * 4;
    int br = tid >> 5, bc = (tid & 31) * 4;
    float acc[8][8];
    #pragma unroll
    for (int i = 0; i < 8; i++)
        #pragma unroll
        for (int j = 0; j < 8; j++) acc[i][j] = 0.f;

    for (int k0 = 0; k0 < K; k0 += BKT) {
        float4 av = make_float4(0.f, 0.f, 0.f, 0.f);
        int grow = bm + ar;
        if (grow < M) av = *(const float4*)(A + (size_t)grow * lda + k0 + ac);
        As[ac + 0][ar] = av.x; As[ac + 1][ar] = av.y;
        As[ac + 2][ar] = av.z; As[ac + 3][ar] = av.w;
        float4 bv = *(const float4*)(B + (size_t)(k0 + br) * ldb + bn + bc);
        *(float4*)&Bs[br][bc] = bv;
        __syncthreads();
        #pragma unroll
        for (int kk = 0; kk < BKT; kk++) {
            float a[8], b[8];
            *(float4*)&a[0] = *(const float4*)&As[kk][ty * 8];
            *(float4*)&a[4] = *(const float4*)&As[kk][ty * 8 + 4];
            *(float4*)&b[0] = *(const float4*)&Bs[kk][tx * 8];
            *(float4*)&b[4] = *(const float4*)&Bs[kk][tx * 8 + 4];
            #pragma unroll
            for (int i = 0; i < 8; i++)
                #pragma unroll
                for (int j = 0; j < 8; j++) acc[i][j] += a[i] * b[j];
        }
        __syncthreads();
    }
    #pragma unroll
    for (int i = 0; i < 8; i++) {
        int row = bm + ty * 8 + i;
        if (row < M) {
            float* cp = C + (size_t)row * ldc + bn + tx * 8;
            if (accflag) {
                #pragma unroll
                for (int j = 0; j < 8; j++) cp[j] += acc[i][j];
            } else {
                *(float4*)cp     = make_float4(acc[i][0], acc[i][1], acc[i][2], acc[i][3]);
                *(float4*)(cp+4) = make_float4(acc[i][4], acc[i][5], acc[i][6], acc[i][7]);
            }
        }
    }
}

// ---------------- MoE expert GEMM (gathered rows, per-expert B, ldb == N) ---
__global__ void __launch_bounds__(256) gemm_moe_kernel(
    int N, int K,
    const float* __restrict__ A, int lda, int use_map,
    const float* __restrict__ Bbase, size_t bstride,
    float* __restrict__ C, int ldc)
{
    int e = blockIdx.z;
    int cnt = g_count[e];
    if ((int)(blockIdx.y * BM) >= cnt) return;
    int base = g_offset[e];
    const float* B = Bbase + (size_t)e * bstride;

    __shared__ float As[BKT][BM];
    __shared__ float Bs[BKT][BN];
    int bm = blockIdx.y * BM, bn = blockIdx.x * BN;
    int tid = threadIdx.x;
    int tx = tid & 15, ty = tid >> 4;
    int ar = tid >> 1, ac = (tid & 1) * 4;
    int br = tid >> 5, bc = (tid & 31) * 4;
    float acc[8][8];
    #pragma unroll
    for (int i = 0; i < 8; i++)
        #pragma unroll
        for (int j = 0; j < 8; j++) acc[i][j] = 0.f;

    int mloc = bm + ar;
    int arow = -1;
    if (mloc < cnt) {
        int slot = base + mloc;
        arow = use_map ? g_slot_token[slot] : slot;
    }
    for (int k0 = 0; k0 < K; k0 += BKT) {
        float4 av = make_float4(0.f, 0.f, 0.f, 0.f);
        if (arow >= 0) av = *(const float4*)(A + (size_t)arow * lda + k0 + ac);
        As[ac + 0][ar] = av.x; As[ac + 1][ar] = av.y;
        As[ac + 2][ar] = av.z; As[ac + 3][ar] = av.w;
        float4 bv = *(const float4*)(B + (size_t)(k0 + br) * N + bn + bc);
        *(float4*)&Bs[br][bc] = bv;
        __syncthreads();
        #pragma unroll
        for (int kk = 0; kk < BKT; kk++) {
            float a[8], b[8];
            *(float4*)&a[0] = *(const float4*)&As[kk][ty * 8];
            *(float4*)&a[4] = *(const float4*)&As[kk][ty * 8 + 4];
            *(float4*)&b[0] = *(const float4*)&Bs[kk][tx * 8];
            *(float4*)&b[4] = *(const float4*)&Bs[kk][tx * 8 + 4];
            #pragma unroll
            for (int i = 0; i < 8; i++)
                #pragma unroll
                for (int j = 0; j < 8; j++) acc[i][j] += a[i] * b[j];
        }
        __syncthreads();
    }
    #pragma unroll
    for (int i = 0; i < 8; i++) {
        int m2 = bm + ty * 8 + i;
        if (m2 < cnt) {
            float* cp = C + (size_t)(base + m2) * ldc + bn + tx * 8;
            *(float4*)cp     = make_float4(acc[i][0], acc[i][1], acc[i][2], acc[i][3]);
            *(float4*)(cp+4) = make_float4(acc[i][4], acc[i][5], acc[i][6], acc[i][7]);
        }
    }
}

// ---------------- RoPE (in-place on g_q, g_k) ----------------
__global__ void rope_kernel() {
    int n = blockIdx.x;
    int pos = n % NT;
    int tid = threadIdx.x;
    const int QW = H * (HD / 2);         // 512
    const int TW = (H + KVH) * (HD / 2); // 640
    for (int w = tid; w < TW; w += 256) {
        float* bp; int i;
        if (w < QW) {
            int hh = w >> 5; i = w & 31;
            bp = g_q + (size_t)n * (H * HD) + hh * HD;
        } else {
            int w2 = w - QW;
            int hh = w2 >> 5; i = w2 & 31;
            bp = g_k + (size_t)n * (KVH * HD) + hh * HD;
        }
        float inv = expf(-(2.0f * (float)i / (float)HD) * 13.815510557964274f);
        float s, c;
        sincosf((float)pos * inv, &s, &c);
        float x1 = bp[2 * i], x2 = bp[2 * i + 1];
        bp[2 * i]     = x1 * c - x2 * s;
        bp[2 * i + 1] = x1 * s + x2 * c;
    }
}

// ---------------- flash attention (causal, GQA) ----------------
__global__ void __launch_bounds__(64) attn_kernel() {
    int bh = blockIdx.x;
    int b = bh / H, h = bh % H;
    int qb = blockIdx.y;
    int tid = threadIdx.x;
    int kvh = h / (H / KVH);
    __shared__ float KV[64 * 64];
    __shared__ float Ss[64 * 65];

    int qi = qb * 64 + tid;
    const float* qptr = g_q + (size_t)(b * NT + qi) * (H * HD) + h * HD;
    float qreg[64], acc[64];
    #pragma unroll
    for (int d = 0; d < 64; d += 4) {
        float4 v = *(const float4*)(qptr + d);
        qreg[d] = v.x; qreg[d+1] = v.y; qreg[d+2] = v.z; qreg[d+3] = v.w;
    }
    #pragma unroll
    for (int d = 0; d < 64; d++) acc[d] = 0.f;
    float m = -1e30f, lsum = 0.f;

    int ntile = qb + 1;
    for (int t0 = 0; t0 < ntile; t0++) {
        int k0 = t0 * 64;
        for (int idx = tid; idx < 64 * 16; idx += 64) {
            int r = idx >> 4, c4 = (idx & 15) << 2;
            size_t kbase = (size_t)(b * NT + k0 + r) * (KVH * HD) + kvh * HD + c4;
            *(float4*)&KV[r * 64 + c4] = *(const float4*)(g_k + kbase);
        }
        __syncthreads();
        float tmax = -1e30f;
        for (int j = 0; j < 64; j++) {
            float s = 0.f;
            const float* kr = &KV[j * 64];
            #pragma unroll
            for (int d = 0; d < 64; d += 4) {
                float4 kv = *(const float4*)(kr + d);
                s += qreg[d] * kv.x + qreg[d+1] * kv.y + qreg[d+2] * kv.z + qreg[d+3] * kv.w;
            }
            s *= 0.125f;
            if (k0 + j > qi) s = -1e30f;
            Ss[tid * 65 + j] = s;
            tmax = fmaxf(tmax, s);
        }
        __syncthreads();
        for (int idx = tid; idx < 64 * 16; idx += 64) {
            int r = idx >> 4, c4 = (idx & 15) << 2;
            size_t vbase = (size_t)(b * NT + k0 + r) * (KVH * HD) + kvh * HD + c4;
            *(float4*)&KV[r * 64 + c4] = *(const float4*)(g_v + vbase);
        }
        __syncthreads();
        float mnew = fmaxf(m, tmax);
        float corr = __expf(m - mnew);
        lsum *= corr;
        #pragma unroll
        for (int d = 0; d < 64; d++) acc[d] *= corr;
        for (int j = 0; j < 64; j++) {
            float p = __expf(Ss[tid * 65 + j] - mnew);
            lsum += p;
            const float* vr = &KV[j * 64];
            #pragma unroll
            for (int d = 0; d < 64; d += 4) {
                float4 vv = *(const float4*)(vr + d);
                acc[d]   += p * vv.x; acc[d+1] += p * vv.y;
                acc[d+2] += p * vv.z; acc[d+3] += p * vv.w;
            }
        }
        m = mnew;
        __syncthreads();
    }
    float inv = 1.f / lsum;
    float* op = g_att + (size_t)(b * NT + qi) * (H * HD) + h * HD;
    #pragma unroll
    for (int d = 0; d < 64; d += 4) {
        float4 o = make_float4(acc[d]*inv, acc[d+1]*inv, acc[d+2]*inv, acc[d+3]*inv);
        *(float4*)(op + d) = o;
    }
}

// ---------------- router + top-2 + aux stats ----------------
__global__ void zero_counters(int zero_aux) {
    int t = threadIdx.x;
    if (t < NE) { g_count[t] = 0; g_mesum[t] = 0.f; }
    if (t == 0 && zero_aux) g_aux[0] = 0.f;
}

__global__ void router_kernel(const float* __restrict__ rw) {
    int n = blockIdx.x, tid = threadIdx.x;
    __shared__ float red[NE][257];
    float acc[NE];
    #pragma unroll
    for (int e = 0; e < NE; e++) acc[e] = 0.f;
    const float* x = g_xn + (size_t)n * D;
    for (int d = tid; d < D; d += 256) {
        float xv = x[d];
        const float* r = rw + (size_t)d * NE;
        #pragma unroll
        for (int e = 0; e < NE; e++) acc[e] += xv * r[e];
    }
    #pragma unroll
    for (int e = 0; e < NE; e++) red[e][tid] = acc[e];
    __syncthreads();
    for (int off = 128; off > 0; off >>= 1) {
        if (tid < off) {
            #pragma unroll
            for (int e = 0; e < NE; e++) red[e][tid] += red[e][tid + off];
        }
        __syncthreads();
    }
    if (tid == 0) {
        float lg[NE], p[NE];
        float mx = -1e30f;
        #pragma unroll
        for (int e = 0; e < NE; e++) { lg[e] = red[e][0]; mx = fmaxf(mx, lg[e]); }
        float sum = 0.f;
        #pragma unroll
        for (int e = 0; e < NE; e++) { p[e] = __expf(lg[e] - mx); sum += p[e]; }
        #pragma unroll
        for (int e = 0; e < NE; e++) p[e] /= sum;
        #pragma unroll
        for (int e = 0; e < NE; e++) atomicAdd(&g_mesum[e], p[e]);
        int i0 = 0;
        #pragma unroll
        for (int e = 1; e < NE; e++) if (p[e] > p[i0]) i0 = e;
        int i1 = (i0 == 0) ? 1 : 0;
        #pragma unroll
        for (int e = 0; e < NE; e++) if (e != i0 && p[e] > p[i1]) i1 = e;
        float g0 = p[i0], g1 = p[i1], gs = g0 + g1;
        g_topk_idx[n * 2] = i0; g_topk_idx[n * 2 + 1] = i1;
        g_topk_gate[n * 2] = g0 / gs; g_topk_gate[n * 2 + 1] = g1 / gs;
        atomicAdd(&g_count[i0], 1);
        atomicAdd(&g_count[i1], 1);
    }
}

__global__ void scan_aux_kernel() {
    if (threadIdx.x == 0) {
        int off = 0;
        float aux = 0.f;
        for (int e = 0; e < NE; e++) {
            g_offset[e] = off;
            off += g_count[e];
            float me = g_mesum[e] / (float)NTOK;
            float ce = (float)g_count[e] / (float)(NTOK * TOPK);
            aux += me * ce;
            g_fill[e] = 0;
        }
        g_aux[0] += (float)NE * aux;
    }
}

__global__ void scatter_kernel() {
    int n = blockIdx.x * blockDim.x + threadIdx.x;
    if (n >= NTOK) return;
    #pragma unroll
    for (int k = 0; k < TOPK; k++) {
        int e = g_topk_idx[n * 2 + k];
        int pos = atomicAdd(&g_fill[e], 1);
        int s = g_offset[e] + pos;
        g_slot_token[s] = n;
        g_slot_of[n * 2 + k] = s;
    }
}

__global__ void silu_mul_kernel() {
    size_t i = ((size_t)blockIdx.x * 256 + threadIdx.x) * 4;
    float4 g = *(float4*)(g_gbuf + i);
    float4 u = *(float4*)(g_ubuf + i);
    g.x = g.x / (1.f + __expf(-g.x)) * u.x;
    g.y = g.y / (1.f + __expf(-g.y)) * u.y;
    g.z = g.z / (1.f + __expf(-g.z)) * u.z;
    g.w = g.w / (1.f + __expf(-g.w)) * u.w;
    *(float4*)(g_gbuf + i) = g;
}

__global__ void combine_kernel() {
    int n = blockIdx.x, tid = threadIdx.x;
    int s0 = g_slot_of[n * 2], s1 = g_slot_of[n * 2 + 1];
    float w0 = g_topk_gate[n * 2], w1 = g_topk_gate[n * 2 + 1];
    int d = tid * 4;
    float4 a  = *(float4*)(g_x + (size_t)n * D + d);
    float4 y0 = *(const float4*)(g_ybuf + (size_t)s0 * D + d);
    float4 y1 = *(const float4*)(g_ybuf + (size_t)s1 * D + d);
    a.x += w0 * y0.x + w1 * y1.x;
    a.y += w0 * y0.y + w1 * y1.y;
    a.z += w0 * y0.z + w1 * y1.z;
    a.w += w0 * y0.w + w1 * y1.w;
    *(float4*)(g_x + (size_t)n * D + d) = a;
}

// ---------------- final heads ----------------
__global__ void mean_kernel() {
    int i = blockIdx.x * 256 + threadIdx.x;
    int b = i / D, d = i % D;
    float s = 0.f;
    for (int t = 0; t < NT; t++) s += g_xn[(size_t)(b * NT + t) * D + d];
    g_xmean[i] = s / (float)NT;
}

#define TASKN 10
#define EVALN 5
__global__ void heads_kernel(const float* __restrict__ task_w, const float* __restrict__ task_b,
                             const float* __restrict__ eval_w, const float* __restrict__ eval_b,
                             float* __restrict__ out) {
    const size_t LOG = (size_t)NTOK * NV;
    int o = blockIdx.x, tid = threadIdx.x;
    if (o == NB * TASKN + NB * EVALN) {
        if (tid == 0) out[LOG + NB * TASKN + NB * EVALN] = g_aux[0];
        return;
    }
    const float* x; const float* w; float bias; size_t oi; int stride;
    if (o < NB * TASKN) {
        int b = o / TASKN, j = o % TASKN;
        x = g_xn + (size_t)(b * NT) * D;
        w = task_w + j; stride = TASKN; bias = task_b[j];
        oi = LOG + b * TASKN + j;
    } else {
        int o2 = o - NB * TASKN;
        int b = o2 / EVALN, j = o2 % EVALN;
        x = g_xmean + (size_t)b * D;
        w = eval_w + j; stride = EVALN; bias = eval_b[j];
        oi = LOG + NB * TASKN + b * EVALN + j;
    }
    float s = 0.f;
    for (int d = tid; d < D; d += 256) s += x[d] * w[(size_t)d * stride];
    __shared__ float red[256];
    red[tid] = s; __syncthreads();
    for (int off = 128; off > 0; off >>= 1) {
        if (tid < off) red[tid] += red[tid + off];
        __syncthreads();
    }
    if (tid == 0) out[oi] = red[0] + bias;
}

// ---------------- launch ----------------
extern "C" void kernel_launch(void* const* d_in, const int* in_sizes, int n_in,
                              void* d_out, int out_size) {
    const int*   ids    = (const int*)  d_in[0];
    const float* emb    = (const float*)d_in[1];
    const float* wq     = (const float*)d_in[2];
    const float* wk     = (const float*)d_in[3];
    const float* wv     = (const float*)d_in[4];
    const float* wo     = (const float*)d_in[5];
    const float* n1     = (const float*)d_in[6];
    const float* n2     = (const float*)d_in[7];
    const float* rw     = (const float*)d_in[8];
    const float* wgte   = (const float*)d_in[9];
    const float* wup    = (const float*)d_in[10];
    const float* wdn    = (const float*)d_in[11];
    const float* nf     = (const float*)d_in[12];
    const float* lmw    = (const float*)d_in[13];
    const float* tw     = (const float*)d_in[14];
    const float* tb     = (const float*)d_in[15];
    const float* ew     = (const float*)d_in[16];
    const float* eb     = (const float*)d_in[17];
    float* out = (float*)d_out;

    float *px, *pxn, *pq, *pk, *pv, *patt, *pg, *pu, *py;
    __nv_bfloat16 *plh, *pll, *pxh, *pxl;
    cudaGetSymbolAddress((void**)&px,   g_x);
    cudaGetSymbolAddress((void**)&pxn,  g_xn);
    cudaGetSymbolAddress((void**)&pq,   g_q);
    cudaGetSymbolAddress((void**)&pk,   g_k);
    cudaGetSymbolAddress((void**)&pv,   g_v);
    cudaGetSymbolAddress((void**)&patt, g_att);
    cudaGetSymbolAddress((void**)&pg,   g_gbuf);
    cudaGetSymbolAddress((void**)&pu,   g_ubuf);
    cudaGetSymbolAddress((void**)&py,   g_ybuf);
    cudaGetSymbolAddress((void**)&plh,  g_lmw_h);
    cudaGetSymbolAddress((void**)&pll,  g_lmw_l);
    cudaGetSymbolAddress((void**)&pxh,  g_xh);
    cudaGetSymbolAddress((void**)&pxl,  g_xl);

    // lm_head weight split+transpose ([D][NV] fp32 -> [NV][D] bf16 hi/lo)
    split_bf16_T_kernel<<<dim3(NV / 32, D / 32), 256>>>(lmw, plh, pll);

    embed_kernel<<<NTOK, 256>>>(ids, emb);
    zero_counters<<<1, 32>>>(1);

    for (int l = 0; l < LNUM; l++) {
        rmsnorm_kernel<<<NTOK, 256>>>(n1 + (size_t)l * D, px, pxn);
        gemm_kernel<<<dim3(8, 16), 256>>>(NTOK, 1024, 1024, pxn, 1024,
                                          wq + (size_t)l * D * 1024, 1024, pq, 1024, 0);
        gemm_kernel<<<dim3(2, 16), 256>>>(NTOK, 256, 1024, pxn, 1024,
                                          wk + (size_t)l * D * 256, 256, pk, 256, 0);
        gemm_kernel<<<dim3(2, 16), 256>>>(NTOK, 256, 1024, pxn, 1024,
                                          wv + (size_t)l * D * 256, 256, pv, 256, 0);
        rope_kernel<<<NTOK, 256>>>();
        attn_kernel<<<dim3(NB * H, NT / 64), 64>>>();
        gemm_kernel<<<dim3(8, 16), 256>>>(NTOK, 1024, 1024, patt, 1024,
                                          wo + (size_t)l * 1024 * D, 1024, px, 1024, 1);

        rmsnorm_kernel<<<NTOK, 256>>>(n2 + (size_t)l * D, px, pxn);
        zero_counters<<<1, 32>>>(0);
        router_kernel<<<NTOK, 256>>>(rw + (size_t)l * D * NE);
        scan_aux_kernel<<<1, 32>>>();
        scatter_kernel<<<NTOK / 256, 256>>>();

        gemm_moe_kernel<<<dim3(FF / 128, 16, NE), 256>>>(
            FF, D, pxn, D, 1, wgte + (size_t)l * NE * D * FF, (size_t)D * FF, pg, FF);
        gemm_moe_kernel<<<dim3(FF / 128, 16, NE), 256>>>(
            FF, D, pxn, D, 1, wup + (size_t)l * NE * D * FF, (size_t)D * FF, pu, FF);
        silu_mul_kernel<<<(NSLOT * FF) / 1024, 256>>>();
        gemm_moe_kernel<<<dim3(D / 128, 16, NE), 256>>>(
            D, FF, pg, FF, 0, wdn + (size_t)l * NE * FF * D, (size_t)FF * D, py, D);
        combine_kernel<<<NTOK, 256>>>();
    }

    rmsnorm_kernel<<<NTOK, 256>>>(nf, px, pxn);
    split_bf16_kernel<<<(NTOK * D / 4) / 256, 256>>>(pxn, pxh, pxl);

    cudaFuncSetAttribute(lmhead_mma_kernel, cudaFuncAttributeMaxDynamicSharedMemorySize, LSM_TOTAL);
    lmhead_mma_kernel<<<dim3(NTOK / 128, NV / 128), 256, LSM_TOTAL>>>(pxh, pxl, plh, pll, out);

    mean_kernel<<<(NB * D) / 256, 256>>>();
    heads_kernel<<<NB * TASKN + NB * EVALN + 1, 256>>>(tw, tb, ew, eb, out);
}

// round 17
// speedup vs baseline: 1.6071x; 1.6071x over previous
#include <cuda_runtime.h>
#include <cuda_bf16.h>
#include <math.h>
#include <stdint.h>

#define LNUM 4
#define D 1024
#define H 16
#define KVH 4
#define HD 64
#define NE 8
#define TOPK 2
#define FF 512
#define NV 32000
#define NB 2
#define NT 1024
#define NTOK (NB*NT)        // 2048
#define NSLOT (NTOK*TOPK)   // 4096
#define EPSV 1e-6f

// ---------------- scratch (static device globals; no allocs) ----------------
__device__ float g_x[NTOK*D];
__device__ float g_xn[NTOK*D];
__device__ float g_q[NTOK*H*HD];
__device__ float g_k[NTOK*KVH*HD];
__device__ float g_v[NTOK*KVH*HD];
__device__ float g_att[NTOK*H*HD];
__device__ float g_gbuf[NSLOT*FF];
__device__ float g_ubuf[NSLOT*FF];
__device__ float g_ybuf[NSLOT*D];
__device__ float g_xmean[NB*D];
__device__ int   g_topk_idx[NTOK*TOPK];
__device__ float g_topk_gate[NTOK*TOPK];
__device__ int   g_count[NE];
__device__ int   g_offset[NE];
__device__ int   g_fill[NE];
__device__ float g_mesum[NE];
__device__ int   g_slot_token[NSLOT];
__device__ int   g_slot_of[NTOK*TOPK];
__device__ float g_aux[1];
// split-bf16 copies for the tensor-core lm_head
// weights stored TRANSPOSED: [NV][D] (n-major) for mma.sync col-B operand
__device__ __nv_bfloat16 g_lmw_h[(size_t)NV*D];
__device__ __nv_bfloat16 g_lmw_l[(size_t)NV*D];
__device__ __nv_bfloat16 g_xh[NTOK*D];
__device__ __nv_bfloat16 g_xl[NTOK*D];

// ==================== smem address helper ============================
__device__ __forceinline__ uint32_t smem_u32(const void* p) {
    uint32_t a;
    asm("{ .reg .u64 t; cvta.to.shared.u64 t, %1; cvt.u32.u64 %0, t; }" : "=r"(a) : "l"(p));
    return a;
}

#define LDSM4(r, addr) \
    asm volatile("ldmatrix.sync.aligned.m8n8.x4.shared.b16 {%0,%1,%2,%3}, [%4];" \
        : "=r"((r)[0]), "=r"((r)[1]), "=r"((r)[2]), "=r"((r)[3]) : "r"(addr))

#define MMA_BF16(c, a, b0, b1) \
    asm volatile("mma.sync.aligned.m16n8k16.row.col.f32.bf16.bf16.f32 " \
        "{%0,%1,%2,%3}, {%4,%5,%6,%7}, {%8,%9}, {%0,%1,%2,%3};" \
        : "+f"((c)[0]), "+f"((c)[1]), "+f"((c)[2]), "+f"((c)[3]) \
        : "r"((a)[0]), "r"((a)[1]), "r"((a)[2]), "r"((a)[3]), "r"(b0), "r"(b1))

__device__ __forceinline__ void cp_async16(uint32_t dst, const void* src) {
    asm volatile("cp.async.ca.shared.global [%0], [%1], 16;" :: "r"(dst), "l"(src));
}
#define CP_COMMIT() asm volatile("cp.async.commit_group;" ::: "memory")
#define CP_WAIT(n)  asm volatile("cp.async.wait_group %0;" :: "n"(n) : "memory")

// ==================== split fp32 -> bf16 hi/lo (same layout) ===============
__global__ void split_bf16_kernel(const float* __restrict__ src,
                                  __nv_bfloat16* __restrict__ hi,
                                  __nv_bfloat16* __restrict__ lo) {
    size_t i = (size_t)blockIdx.x * 256 + threadIdx.x;
    float4 v = *(const float4*)(src + i * 4);
    float vv[4] = {v.x, v.y, v.z, v.w};
    ushort4 hb, lb;
    unsigned short* hp = &hb.x;
    unsigned short* lp = &lb.x;
    #pragma unroll
    for (int j = 0; j < 4; j++) {
        __nv_bfloat16 h = __float2bfloat16(vv[j]);
        __nv_bfloat16 l = __float2bfloat16(vv[j] - __bfloat162float(h));
        hp[j] = __bfloat16_as_ushort(h);
        lp[j] = __bfloat16_as_ushort(l);
    }
    *(ushort4*)((unsigned short*)hi + i * 4) = hb;
    *(ushort4*)((unsigned short*)lo + i * 4) = lb;
}

// ==================== transposed split: src [D][NV] -> hi/lo [NV][D] ========
__global__ void split_bf16_T_kernel(const float* __restrict__ src,
                                    __nv_bfloat16* __restrict__ hi,
                                    __nv_bfloat16* __restrict__ lo) {
    __shared__ float t[32][33];
    int n0 = blockIdx.x * 32, k0 = blockIdx.y * 32;
    int tx = threadIdx.x & 31, ty = threadIdx.x >> 5;   // 32 x 8
    #pragma unroll
    for (int i = 0; i < 4; i++)
        t[ty + i * 8][tx] = src[(size_t)(k0 + ty + i * 8) * NV + n0 + tx];
    __syncthreads();
    #pragma unroll
    for (int i = 0; i < 4; i++) {
        int n = ty + i * 8;
        float v = t[tx][n];       // = src[k0+tx][n0+n]
        __nv_bfloat16 h = __float2bfloat16(v);
        __nv_bfloat16 l = __float2bfloat16(v - __bfloat162float(h));
        hi[(size_t)(n0 + n) * D + k0 + tx] = h;
        lo[(size_t)(n0 + n) * D + k0 + tx] = l;
    }
}

// ==================== lm_head via mma.sync (HMMA) + cp.async ================
// C[2048,32000] = A[2048,1024] @ B^T, A row-major [M][K], B n-major [N][K].
// Split-bf16: C = Ah*Bh + Ah*Bl + Al*Bh (fp32 accum). Tile 128x128x32.
// cp.async gmem->smem (no register staging => no spills), double buffered.
#define LPAD 40                              // smem row stride (bf16 elems); 80B, 16B-aligned rows
#define LTILE (128*LPAD*2)                   // 10240 B per tile
#define LBUF  (4*LTILE)                      // Ah|Al|Bh|Bl = 40960 B
#define LSM_TOTAL (2*LBUF)                   // 81920 B
__global__ void __launch_bounds__(256) lmhead_mma_kernel(
    const __nv_bfloat16* __restrict__ Ah, const __nv_bfloat16* __restrict__ Al,
    const __nv_bfloat16* __restrict__ BhT, const __nv_bfloat16* __restrict__ BlT,
    float* __restrict__ out)
{
    extern __shared__ char smem[];
    const int tid = threadIdx.x, wid = tid >> 5, lane = tid & 31;
    const int m0 = blockIdx.x * 128, n0 = blockIdx.y * 128;
    const int wm = (wid & 1) * 64, wn = (wid >> 1) * 32;
    uint32_t sb = smem_u32(smem);

    float acc[4][4][4];
    #pragma unroll
    for (int mi = 0; mi < 4; mi++)
        #pragma unroll
        for (int ni = 0; ni < 4; ni++)
            #pragma unroll
            for (int e = 0; e < 4; e++) acc[mi][ni][e] = 0.f;

    // async tile loader: 4 tiles x 512 16B-chunks, 8 cp.async per thread
    auto load_tiles = [&](int buf, int ks) {
        int k0 = ks * 32;
        uint32_t base = sb + buf * LBUF;
        #pragma unroll
        for (int t = 0; t < 4; t++) {
            const __nv_bfloat16* src = (t == 0) ? Ah : (t == 1) ? Al : (t == 2) ? BhT : BlT;
            int rbase = (t < 2) ? m0 : n0;
            #pragma unroll
            for (int i = 0; i < 2; i++) {
                int w = tid + i * 256;          // 0..511
                int row = w >> 2, cc = (w & 3) * 8;
                cp_async16(base + t * LTILE + (row * LPAD + cc) * 2,
                           src + (size_t)(rbase + row) * D + k0 + cc);
            }
        }
        CP_COMMIT();
    };

    load_tiles(0, 0);

    for (int ks = 0; ks < 32; ks++) {
        int cur = ks & 1;
        if (ks + 1 < 32) {
            load_tiles(cur ^ 1, ks + 1);
            CP_WAIT(1);        // current buffer's group complete (1 pending: next)
        } else {
            CP_WAIT(0);
        }
        __syncthreads();       // all threads' deposits visible

        uint32_t ab  = sb + cur * LBUF;
        uint32_t alb = ab + LTILE;
        uint32_t bb  = ab + 2 * LTILE;
        uint32_t blb = ab + 3 * LTILE;
        #pragma unroll
        for (int kk = 0; kk < 2; kk++) {
            uint32_t ah[4][4], al[4][4], bh[2][4], bl[2][4];
            int acol = kk * 16 + (lane >> 4) * 8;
            #pragma unroll
            for (int mi = 0; mi < 4; mi++) {
                uint32_t off = ((wm + mi * 16 + (lane & 15)) * LPAD + acol) * 2;
                LDSM4(ah[mi], ab + off);
                LDSM4(al[mi], alb + off);
            }
            int bcol = kk * 16 + ((lane >> 3) & 1) * 8;
            #pragma unroll
            for (int g = 0; g < 2; g++) {
                int nrow = wn + g * 16 + ((lane >> 4) << 3) + (lane & 7);
                uint32_t off = (nrow * LPAD + bcol) * 2;
                LDSM4(bh[g], bb + off);
                LDSM4(bl[g], blb + off);
            }
            #pragma unroll
            for (int mi = 0; mi < 4; mi++)
                #pragma unroll
                for (int ni = 0; ni < 4; ni++) {
                    int g = ni >> 1, s = (ni & 1) * 2;
                    MMA_BF16(acc[mi][ni], ah[mi], bh[g][s], bh[g][s + 1]);
                    MMA_BF16(acc[mi][ni], ah[mi], bl[g][s], bl[g][s + 1]);
                    MMA_BF16(acc[mi][ni], al[mi], bh[g][s], bh[g][s + 1]);
                }
        }
        __syncthreads();       // done reading cur before it is overwritten (iter ks+2)
    }

    // epilogue: c0,c1 -> (row, col..col+1); c2,c3 -> (row+8, col..col+1)
    #pragma unroll
    for (int mi = 0; mi < 4; mi++) {
        int row = m0 + wm + mi * 16 + (lane >> 2);
        #pragma unroll
        for (int ni = 0; ni < 4; ni++) {
            int col = n0 + wn + ni * 8 + (lane & 3) * 2;
            float* p = out + (size_t)row * NV + col;
            float2 v0 = make_float2(acc[mi][ni][0], acc[mi][ni][1]);
            float2 v1 = make_float2(acc[mi][ni][2], acc[mi][ni][3]);
            *(float2*)p = v0;
            *(float2*)(p + (size_t)8 * NV) = v1;
        }
    }
}

// ---------------- embedding ----------------
__global__ void embed_kernel(const int* __restrict__ ids, const float* __restrict__ emb) {
    int n = blockIdx.x;
    int id = ids[n];
    int d = threadIdx.x * 4;
    float4 v = *(const float4*)(emb + (size_t)id * D + d);
    *(float4*)(g_x + (size_t)n * D + d) = v;
}

// ---------------- rmsnorm ----------------
__global__ void rmsnorm_kernel(const float* __restrict__ w,
                               const float* __restrict__ src,
                               float* __restrict__ dst) {
    int n = blockIdx.x, tid = threadIdx.x;
    const float* x = src + (size_t)n * D;
    float ss = 0.f;
    for (int d = tid; d < D; d += 256) { float v = x[d]; ss += v * v; }
    __shared__ float red[256];
    red[tid] = ss; __syncthreads();
    for (int off = 128; off > 0; off >>= 1) {
        if (tid < off) red[tid] += red[tid + off];
        __syncthreads();
    }
    __shared__ float s_scale;
    if (tid == 0) s_scale = rsqrtf(red[0] / (float)D + EPSV);
    __syncthreads();
    float sc = s_scale;
    float* o = dst + (size_t)n * D;
    for (int d = tid; d < D; d += 256) o[d] = w[d] * x[d] * sc;
}

// ---------------- generic SGEMM: C[M,N] = A[M,K] @ B[K,N] (+C if acc) ------
#define BM 128
#define BN 128
#define BKT 8
__global__ void __launch_bounds__(256) gemm_kernel(
    int M, int N, int K,
    const float* __restrict__ A, int lda,
    const float* __restrict__ B, int ldb,
    float* __restrict__ C, int ldc, int accflag)
{
    __shared__ float As[BKT][BM];
    __shared__ float Bs[BKT][BN];
    int bm = blockIdx.y * BM, bn = blockIdx.x * BN;
    int tid = threadIdx.x;
    int tx = tid & 15, ty = tid >> 4;
    int ar = tid >> 1, ac = (tid & 1) * 4;
    int br = tid >> 5, bc = (tid & 31) * 4;
    float acc[8][8];
    #pragma unroll
    for (int i = 0; i < 8; i++)
        #pragma unroll
        for (int j = 0; j < 8; j++) acc[i][j] = 0.f;

    for (int k0 = 0; k0 < K; k0 += BKT) {
        float4 av = make_float4(0.f, 0.f, 0.f, 0.f);
        int grow = bm + ar;
        if (grow < M) av = *(const float4*)(A + (size_t)grow * lda + k0 + ac);
        As[ac + 0][ar] = av.x; As[ac + 1][ar] = av.y;
        As[ac + 2][ar] = av.z; As[ac + 3][ar] = av.w;
        float4 bv = *(const float4*)(B + (size_t)(k0 + br) * ldb + bn + bc);
        *(float4*)&Bs[br][bc] = bv;
        __syncthreads();
        #pragma unroll
        for (int kk = 0; kk < BKT; kk++) {
            float a[8], b[8];
            *(float4*)&a[0] = *(const float4*)&As[kk][ty * 8];
            *(float4*)&a[4] = *(const float4*)&As[kk][ty * 8 + 4];
            *(float4*)&b[0] = *(const float4*)&Bs[kk][tx * 8];
            *(float4*)&b[4] = *(const float4*)&Bs[kk][tx * 8 + 4];
            #pragma unroll
            for (int i = 0; i < 8; i++)
                #pragma unroll
                for (int j = 0; j < 8; j++) acc[i][j] += a[i] * b[j];
        }
        __syncthreads();
    }
    #pragma unroll
    for (int i = 0; i < 8; i++) {
        int row = bm + ty * 8 + i;
        if (row < M) {
            float* cp = C + (size_t)row * ldc + bn + tx * 8;
            if (accflag) {
                #pragma unroll
                for (int j = 0; j < 8; j++) cp[j] += acc[i][j];
            } else {
                *(float4*)cp     = make_float4(acc[i][0], acc[i][1], acc[i][2], acc[i][3]);
                *(float4*)(cp+4) = make_float4(acc[i][4], acc[i][5], acc[i][6], acc[i][7]);
            }
        }
    }
}

// ---------------- MoE expert GEMM (gathered rows, per-expert B, ldb == N) ---
__global__ void __launch_bounds__(256) gemm_moe_kernel(
    int N, int K,
    const float* __restrict__ A, int lda, int use_map,
    const float* __restrict__ Bbase, size_t bstride,
    float* __restrict__ C, int ldc)
{
    int e = blockIdx.z;
    int cnt = g_count[e];
    if ((int)(blockIdx.y * BM) >= cnt) return;
    int base = g_offset[e];
    const float* B = Bbase + (size_t)e * bstride;

    __shared__ float As[BKT][BM];
    __shared__ float Bs[BKT][BN];
    int bm = blockIdx.y * BM, bn = blockIdx.x * BN;
    int tid = threadIdx.x;
    int tx = tid & 15, ty = tid >> 4;
    int ar = tid >> 1, ac = (tid & 1) * 4;
    int br = tid >> 5, bc = (tid & 31) * 4;
    float acc[8][8];
    #pragma unroll
    for (int i = 0; i < 8; i++)
        #pragma unroll
        for (int j = 0; j < 8; j++) acc[i][j] = 0.f;

    int mloc = bm + ar;
    int arow = -1;
    if (mloc < cnt) {
        int slot = base + mloc;
        arow = use_map ? g_slot_token[slot] : slot;
    }
    for (int k0 = 0; k0 < K; k0 += BKT) {
        float4 av = make_float4(0.f, 0.f, 0.f, 0.f);
        if (arow >= 0) av = *(const float4*)(A + (size_t)arow * lda + k0 + ac);
        As[ac + 0][ar] = av.x; As[ac + 1][ar] = av.y;
        As[ac + 2][ar] = av.z; As[ac + 3][ar] = av.w;
        float4 bv = *(const float4*)(B + (size_t)(k0 + br) * N + bn + bc);
        *(float4*)&Bs[br][bc] = bv;
        __syncthreads();
        #pragma unroll
        for (int kk = 0; kk < BKT; kk++) {
            float a[8], b[8];
            *(float4*)&a[0] = *(const float4*)&As[kk][ty * 8];
            *(float4*)&a[4] = *(const float4*)&As[kk][ty * 8 + 4];
            *(float4*)&b[0] = *(const float4*)&Bs[kk][tx * 8];
            *(float4*)&b[4] = *(const float4*)&Bs[kk][tx * 8 + 4];
            #pragma unroll
            for (int i = 0; i < 8; i++)
                #pragma unroll
                for (int j = 0; j < 8; j++) acc[i][j] += a[i] * b[j];
        }
        __syncthreads();
    }
    #pragma unroll
    for (int i = 0; i < 8; i++) {
        int m2 = bm + ty * 8 + i;
        if (m2 < cnt) {
            float* cp = C + (size_t)(base + m2) * ldc + bn + tx * 8;
            *(float4*)cp     = make_float4(acc[i][0], acc[i][1], acc[i][2], acc[i][3]);
            *(float4*)(cp+4) = make_float4(acc[i][4], acc[i][5], acc[i][6], acc[i][7]);
        }
    }
}

// ---------------- RoPE (in-place on g_q, g_k) ----------------
__global__ void rope_kernel() {
    int n = blockIdx.x;
    int pos = n % NT;
    int tid = threadIdx.x;
    const int QW = H * (HD / 2);         // 512
    const int TW = (H + KVH) * (HD / 2); // 640
    for (int w = tid; w < TW; w += 256) {
        float* bp; int i;
        if (w < QW) {
            int hh = w >> 5; i = w & 31;
            bp = g_q + (size_t)n * (H * HD) + hh * HD;
        } else {
            int w2 = w - QW;
            int hh = w2 >> 5; i = w2 & 31;
            bp = g_k + (size_t)n * (KVH * HD) + hh * HD;
        }
        float inv = expf(-(2.0f * (float)i / (float)HD) * 13.815510557964274f);
        float s, c;
        sincosf((float)pos * inv, &s, &c);
        float x1 = bp[2 * i], x2 = bp[2 * i + 1];
        bp[2 * i]     = x1 * c - x2 * s;
        bp[2 * i + 1] = x1 * s + x2 * c;
    }
}

// ---------------- flash attention (causal, GQA) ----------------
__global__ void __launch_bounds__(64) attn_kernel() {
    int bh = blockIdx.x;
    int b = bh / H, h = bh % H;
    int qb = blockIdx.y;
    int tid = threadIdx.x;
    int kvh = h / (H / KVH);
    __shared__ float KV[64 * 64];
    __shared__ float Ss[64 * 65];

    int qi = qb * 64 + tid;
    const float* qptr = g_q + (size_t)(b * NT + qi) * (H * HD) + h * HD;
    float qreg[64], acc[64];
    #pragma unroll
    for (int d = 0; d < 64; d += 4) {
        float4 v = *(const float4*)(qptr + d);
        qreg[d] = v.x; qreg[d+1] = v.y; qreg[d+2] = v.z; qreg[d+3] = v.w;
    }
    #pragma unroll
    for (int d = 0; d < 64; d++) acc[d] = 0.f;
    float m = -1e30f, lsum = 0.f;

    int ntile = qb + 1;
    for (int t0 = 0; t0 < ntile; t0++) {
        int k0 = t0 * 64;
        for (int idx = tid; idx < 64 * 16; idx += 64) {
            int r = idx >> 4, c4 = (idx & 15) << 2;
            size_t kbase = (size_t)(b * NT + k0 + r) * (KVH * HD) + kvh * HD + c4;
            *(float4*)&KV[r * 64 + c4] = *(const float4*)(g_k + kbase);
        }
        __syncthreads();
        float tmax = -1e30f;
        for (int j = 0; j < 64; j++) {
            float s = 0.f;
            const float* kr = &KV[j * 64];
            #pragma unroll
            for (int d = 0; d < 64; d += 4) {
                float4 kv = *(const float4*)(kr + d);
                s += qreg[d] * kv.x + qreg[d+1] * kv.y + qreg[d+2] * kv.z + qreg[d+3] * kv.w;
            }
            s *= 0.125f;
            if (k0 + j > qi) s = -1e30f;
            Ss[tid * 65 + j] = s;
            tmax = fmaxf(tmax, s);
        }
        __syncthreads();
        for (int idx = tid; idx < 64 * 16; idx += 64) {
            int r = idx >> 4, c4 = (idx & 15) << 2;
            size_t vbase = (size_t)(b * NT + k0 + r) * (KVH * HD) + kvh * HD + c4;
            *(float4*)&KV[r * 64 + c4] = *(const float4*)(g_v + vbase);
        }
        __syncthreads();
        float mnew = fmaxf(m, tmax);
        float corr = __expf(m - mnew);
        lsum *= corr;
        #pragma unroll
        for (int d = 0; d < 64; d++) acc[d] *= corr;
        for (int j = 0; j < 64; j++) {
            float p = __expf(Ss[tid * 65 + j] - mnew);
            lsum += p;
            const float* vr = &KV[j * 64];
            #pragma unroll
            for (int d = 0; d < 64; d += 4) {
                float4 vv = *(const float4*)(vr + d);
                acc[d]   += p * vv.x; acc[d+1] += p * vv.y;
                acc[d+2] += p * vv.z; acc[d+3] += p * vv.w;
            }
        }
        m = mnew;
        __syncthreads();
    }
    float inv = 1.f / lsum;
    float* op = g_att + (size_t)(b * NT + qi) * (H * HD) + h * HD;
    #pragma unroll
    for (int d = 0; d < 64; d += 4) {
        float4 o = make_float4(acc[d]*inv, acc[d+1]*inv, acc[d+2]*inv, acc[d+3]*inv);
        *(float4*)(op + d) = o;
    }
}

// ---------------- router + top-2 + aux stats ----------------
__global__ void zero_counters(int zero_aux) {
    int t = threadIdx.x;
    if (t < NE) { g_count[t] = 0; g_mesum[t] = 0.f; }
    if (t == 0 && zero_aux) g_aux[0] = 0.f;
}

__global__ void router_kernel(const float* __restrict__ rw) {
    int n = blockIdx.x, tid = threadIdx.x;
    __shared__ float red[NE][257];
    float acc[NE];
    #pragma unroll
    for (int e = 0; e < NE; e++) acc[e] = 0.f;
    const float* x = g_xn + (size_t)n * D;
    for (int d = tid; d < D; d += 256) {
        float xv = x[d];
        const float* r = rw + (size_t)d * NE;
        #pragma unroll
        for (int e = 0; e < NE; e++) acc[e] += xv * r[e];
    }
    #pragma unroll
    for (int e = 0; e < NE; e++) red[e][tid] = acc[e];
    __syncthreads();
    for (int off = 128; off > 0; off >>= 1) {
        if (tid < off) {
            #pragma unroll
            for (int e = 0; e < NE; e++) red[e][tid] += red[e][tid + off];
        }
        __syncthreads();
    }
    if (tid == 0) {
        float lg[NE], p[NE];
        float mx = -1e30f;
        #pragma unroll
        for (int e = 0; e < NE; e++) { lg[e] = red[e][0]; mx = fmaxf(mx, lg[e]); }
        float sum = 0.f;
        #pragma unroll
        for (int e = 0; e < NE; e++) { p[e] = __expf(lg[e] - mx); sum += p[e]; }
        #pragma unroll
        for (int e = 0; e < NE; e++) p[e] /= sum;
        #pragma unroll
        for (int e = 0; e < NE; e++) atomicAdd(&g_mesum[e], p[e]);
        int i0 = 0;
        #pragma unroll
        for (int e = 1; e < NE; e++) if (p[e] > p[i0]) i0 = e;
        int i1 = (i0 == 0) ? 1 : 0;
        #pragma unroll
        for (int e = 0; e < NE; e++) if (e != i0 && p[e] > p[i1]) i1 = e;
        float g0 = p[i0], g1 = p[i1], gs = g0 + g1;
        g_topk_idx[n * 2] = i0; g_topk_idx[n * 2 + 1] = i1;
        g_topk_gate[n * 2] = g0 / gs; g_topk_gate[n * 2 + 1] = g1 / gs;
        atomicAdd(&g_count[i0], 1);
        atomicAdd(&g_count[i1], 1);
    }
}

__global__ void scan_aux_kernel() {
    if (threadIdx.x == 0) {
        int off = 0;
        float aux = 0.f;
        for (int e = 0; e < NE; e++) {
            g_offset[e] = off;
            off += g_count[e];
            float me = g_mesum[e] / (float)NTOK;
            float ce = (float)g_count[e] / (float)(NTOK * TOPK);
            aux += me * ce;
            g_fill[e] = 0;
        }
        g_aux[0] += (float)NE * aux;
    }
}

__global__ void scatter_kernel() {
    int n = blockIdx.x * blockDim.x + threadIdx.x;
    if (n >= NTOK) return;
    #pragma unroll
    for (int k = 0; k < TOPK; k++) {
        int e = g_topk_idx[n * 2 + k];
        int pos = atomicAdd(&g_fill[e], 1);
        int s = g_offset[e] + pos;
        g_slot_token[s] = n;
        g_slot_of[n * 2 + k] = s;
    }
}

__global__ void silu_mul_kernel() {
    size_t i = ((size_t)blockIdx.x * 256 + threadIdx.x) * 4;
    float4 g = *(float4*)(g_gbuf + i);
    float4 u = *(float4*)(g_ubuf + i);
    g.x = g.x / (1.f + __expf(-g.x)) * u.x;
    g.y = g.y / (1.f + __expf(-g.y)) * u.y;
    g.z = g.z / (1.f + __expf(-g.z)) * u.z;
    g.w = g.w / (1.f + __expf(-g.w)) * u.w;
    *(float4*)(g_gbuf + i) = g;
}

__global__ void combine_kernel() {
    int n = blockIdx.x, tid = threadIdx.x;
    int s0 = g_slot_of[n * 2], s1 = g_slot_of[n * 2 + 1];
    float w0 = g_topk_gate[n * 2], w1 = g_topk_gate[n * 2 + 1];
    int d = tid * 4;
    float4 a  = *(float4*)(g_x + (size_t)n * D + d);
    float4 y0 = *(const float4*)(g_ybuf + (size_t)s0 * D + d);
    float4 y1 = *(const float4*)(g_ybuf + (size_t)s1 * D + d);
    a.x += w0 * y0.x + w1 * y1.x;
    a.y += w0 * y0.y + w1 * y1.y;
    a.z += w0 * y0.z + w1 * y1.z;
    a.w += w0 * y0.w + w1 * y1.w;
    *(float4*)(g_x + (size_t)n * D + d) = a;
}

// ---------------- final heads ----------------
__global__ void mean_kernel() {
    int i = blockIdx.x * 256 + threadIdx.x;
    int b = i / D, d = i % D;
    float s = 0.f;
    for (int t = 0; t < NT; t++) s += g_xn[(size_t)(b * NT + t) * D + d];
    g_xmean[i] = s / (float)NT;
}

#define TASKN 10
#define EVALN 5
__global__ void heads_kernel(const float* __restrict__ task_w, const float* __restrict__ task_b,
                             const float* __restrict__ eval_w, const float* __restrict__ eval_b,
                             float* __restrict__ out) {
    const size_t LOG = (size_t)NTOK * NV;
    int o = blockIdx.x, tid = threadIdx.x;
    if (o == NB * TASKN + NB * EVALN) {
        if (tid == 0) out[LOG + NB * TASKN + NB * EVALN] = g_aux[0];
        return;
    }
    const float* x; const float* w; float bias; size_t oi; int stride;
    if (o < NB * TASKN) {
        int b = o / TASKN, j = o % TASKN;
        x = g_xn + (size_t)(b * NT) * D;
        w = task_w + j; stride = TASKN; bias = task_b[j];
        oi = LOG + b * TASKN + j;
    } else {
        int o2 = o - NB * TASKN;
        int b = o2 / EVALN, j = o2 % EVALN;
        x = g_xmean + (size_t)b * D;
        w = eval_w + j; stride = EVALN; bias = eval_b[j];
        oi = LOG + NB * TASKN + b * EVALN + j;
    }
    float s = 0.f;
    for (int d = tid; d < D; d += 256) s += x[d] * w[(size_t)d * stride];
    __shared__ float red[256];
    red[tid] = s; __syncthreads();
    for (int off = 128; off > 0; off >>= 1) {
        if (tid < off) red[tid] += red[tid + off];
        __syncthreads();
    }
    if (tid == 0) out[oi] = red[0] + bias;
}

// ---------------- launch ----------------
extern "C" void kernel_launch(void* const* d_in, const int* in_sizes, int n_in,
                              void* d_out, int out_size) {
    const int*   ids    = (const int*)  d_in[0];
    const float* emb    = (const float*)d_in[1];
    const float* wq     = (const float*)d_in[2];
    const float* wk     = (const float*)d_in[3];
    const float* wv     = (const float*)d_in[4];
    const float* wo     = (const float*)d_in[5];
    const float* n1     = (const float*)d_in[6];
    const float* n2     = (const float*)d_in[7];
    const float* rw     = (const float*)d_in[8];
    const float* wgte   = (const float*)d_in[9];
    const float* wup    = (const float*)d_in[10];
    const float* wdn    = (const float*)d_in[11];
    const float* nf     = (const float*)d_in[12];
    const float* lmw    = (const float*)d_in[13];
    const float* tw     = (const float*)d_in[14];
    const float* tb     = (const float*)d_in[15];
    const float* ew     = (const float*)d_in[16];
    const float* eb     = (const float*)d_in[17];
    float* out = (float*)d_out;

    float *px, *pxn, *pq, *pk, *pv, *patt, *pg, *pu, *py;
    __nv_bfloat16 *plh, *pll, *pxh, *pxl;
    cudaGetSymbolAddress((void**)&px,   g_x);
    cudaGetSymbolAddress((void**)&pxn,  g_xn);
    cudaGetSymbolAddress((void**)&pq,   g_q);
    cudaGetSymbolAddress((void**)&pk,   g_k);
    cudaGetSymbolAddress((void**)&pv,   g_v);
    cudaGetSymbolAddress((void**)&patt, g_att);
    cudaGetSymbolAddress((void**)&pg,   g_gbuf);
    cudaGetSymbolAddress((void**)&pu,   g_ubuf);
    cudaGetSymbolAddress((void**)&py,   g_ybuf);
    cudaGetSymbolAddress((void**)&plh,  g_lmw_h);
    cudaGetSymbolAddress((void**)&pll,  g_lmw_l);
    cudaGetSymbolAddress((void**)&pxh,  g_xh);
    cudaGetSymbolAddress((void**)&pxl,  g_xl);

    // lm_head weight split+transpose ([D][NV] fp32 -> [NV][D] bf16 hi/lo)
    split_bf16_T_kernel<<<dim3(NV / 32, D / 32), 256>>>(lmw, plh, pll);

    embed_kernel<<<NTOK, 256>>>(ids, emb);
    zero_counters<<<1, 32>>>(1);

    for (int l = 0; l < LNUM; l++) {
        rmsnorm_kernel<<<NTOK, 256>>>(n1 + (size_t)l * D, px, pxn);
        gemm_kernel<<<dim3(8, 16), 256>>>(NTOK, 1024, 1024, pxn, 1024,
                                          wq + (size_t)l * D * 1024, 1024, pq, 1024, 0);
        gemm_kernel<<<dim3(2, 16), 256>>>(NTOK, 256, 1024, pxn, 1024,
                                          wk + (size_t)l * D * 256, 256, pk, 256, 0);
        gemm_kernel<<<dim3(2, 16), 256>>>(NTOK, 256, 1024, pxn, 1024,
                                          wv + (size_t)l * D * 256, 256, pv, 256, 0);
        rope_kernel<<<NTOK, 256>>>();
        attn_kernel<<<dim3(NB * H, NT / 64), 64>>>();
        gemm_kernel<<<dim3(8, 16), 256>>>(NTOK, 1024, 1024, patt, 1024,
                                          wo + (size_t)l * 1024 * D, 1024, px, 1024, 1);

        rmsnorm_kernel<<<NTOK, 256>>>(n2 + (size_t)l * D, px, pxn);
        zero_counters<<<1, 32>>>(0);
        router_kernel<<<NTOK, 256>>>(rw + (size_t)l * D * NE);
        scan_aux_kernel<<<1, 32>>>();
        scatter_kernel<<<NTOK / 256, 256>>>();

        gemm_moe_kernel<<<dim3(FF / 128, 16, NE), 256>>>(
            FF, D, pxn, D, 1, wgte + (size_t)l * NE * D * FF, (size_t)D * FF, pg, FF);
        gemm_moe_kernel<<<dim3(FF / 128, 16, NE), 256>>>(
            FF, D, pxn, D, 1, wup + (size_t)l * NE * D * FF, (size_t)D * FF, pu, FF);
        silu_mul_kernel<<<(NSLOT * FF) / 1024, 256>>>();
        gemm_moe_kernel<<<dim3(D / 128, 16, NE), 256>>>(
            D, FF, pg, FF, 0, wdn + (size_t)l * NE * FF * D, (size_t)FF * D, py, D);
        combine_kernel<<<NTOK, 256>>>();
    }

    rmsnorm_kernel<<<NTOK, 256>>>(nf, px, pxn);
    split_bf16_kernel<<<(NTOK * D / 4) / 256, 256>>>(pxn, pxh, pxl);

    cudaFuncSetAttribute(lmhead_mma_kernel, cudaFuncAttributeMaxDynamicSharedMemorySize, LSM_TOTAL);
    lmhead_mma_kernel<<<dim3(NTOK / 128, NV / 128), 256, LSM_TOTAL>>>(pxh, pxl, plh, pll, out);

    mean_kernel<<<(NB * D) / 256, 256>>>();
    heads_kernel<<<NB * TASKN + NB * EVALN + 1, 256>>>(tw, tb, ew, eb, out);
}